// round 5
// baseline (speedup 1.0000x reference)
#include <cuda_runtime.h>
#include <cuda_bf16.h>
#include <stdint.h>
#include <math.h>

#define B_   8
#define T_   2048
#define DIM_ 512
#define NH_  8
#define NKV_ 4
#define HD_  64
#define KVD_ (NKV_*HD_)
#define BT_  (B_*T_)

// fp32 scratch
__device__ float g_q[(size_t)BT_*DIM_];
__device__ float g_k[(size_t)BT_*KVD_];
// bf16 split scratch (hi/lo)
__device__ uint16_t g_xh[(size_t)BT_*DIM_],  g_xl[(size_t)BT_*DIM_];
__device__ uint16_t g_qh[(size_t)BT_*DIM_],  g_ql[(size_t)BT_*DIM_];
__device__ uint16_t g_kh[(size_t)BT_*KVD_],  g_kl[(size_t)BT_*KVD_];
__device__ uint16_t g_vh[(size_t)BT_*KVD_],  g_vl[(size_t)BT_*KVD_];
__device__ uint16_t g_yh[(size_t)BT_*DIM_],  g_yl[(size_t)BT_*DIM_];
__device__ uint16_t g_wqh[DIM_*DIM_], g_wql[DIM_*DIM_];
__device__ uint16_t g_wkh[KVD_*DIM_], g_wkl[KVD_*DIM_];
__device__ uint16_t g_wvh[KVD_*DIM_], g_wvl[KVD_*DIM_];
__device__ uint16_t g_wph[DIM_*DIM_], g_wpl[DIM_*DIM_];
// rope tables
__device__ float g_cos[T_*32], g_sin[T_*32];

#define MMA_BF16(d, a, b) asm volatile( \
  "mma.sync.aligned.m16n8k16.row.col.f32.bf16.bf16.f32 " \
  "{%0,%1,%2,%3}, {%4,%5,%6,%7}, {%8,%9}, {%0,%1,%2,%3};\n" \
  : "+f"(d[0]), "+f"(d[1]), "+f"(d[2]), "+f"(d[3]) \
  : "r"(a[0]), "r"(a[1]), "r"(a[2]), "r"(a[3]), "r"(b[0]), "r"(b[1]))

#define LDMX2T(r0, r1, a) asm volatile( \
  "ldmatrix.sync.aligned.m8n8.x2.trans.shared.b16 {%0,%1}, [%2];" \
  : "=r"(r0), "=r"(r1) : "r"(a))

__device__ __forceinline__ void split2(float f, uint16_t& h, uint16_t& l)
{
    __nv_bfloat16 hb = __float2bfloat16_rn(f);
    float r = f - __bfloat162float(hb);
    __nv_bfloat16 lb = __float2bfloat16_rn(r);
    h = *(uint16_t*)&hb;
    l = *(uint16_t*)&lb;
}

// generic fp32 -> (hi,lo) bf16 splitter, 4 elems/thread
__global__ void split4(const float* __restrict__ a,
                       uint16_t* __restrict__ ah, uint16_t* __restrict__ al, int n4)
{
    int i = blockIdx.x * blockDim.x + threadIdx.x;
    if (i >= n4) return;
    float4 f = ((const float4*)a)[i];
    uint16_t h0,l0,h1,l1,h2,l2,h3,l3;
    split2(f.x,h0,l0); split2(f.y,h1,l1); split2(f.z,h2,l2); split2(f.w,h3,l3);
    ((uint2*)ah)[i] = make_uint2((uint32_t)h0 | ((uint32_t)h1<<16),
                                 (uint32_t)h2 | ((uint32_t)h3<<16));
    ((uint2*)al)[i] = make_uint2((uint32_t)l0 | ((uint32_t)l1<<16),
                                 (uint32_t)l2 | ((uint32_t)l3<<16));
}

// rope cos/sin tables (double-precision freq, matches fp32 ref within tolerance)
__global__ void rope_tables(float* __restrict__ ctab, float* __restrict__ stab)
{
    int i = blockIdx.x * blockDim.x + threadIdx.x;
    if (i >= T_*32) return;
    int t = i >> 5, j = i & 31;
    double invf = pow(10000.0, -(double)(2*j) / (double)HD_);
    float ang = (float)((double)t * invf);
    float s, c;
    sincosf(ang, &s, &c);
    ctab[i] = c; stab[i] = s;
}

// ---------------------------------------------------------------------------
// Pre-split bf16 tensor-core GEMM: C[M,N] = (Ah+Al)[M,K] @ (Bh+Bl)[N,K]^T
// 3-product split. If Ch != null, writes split bf16 output instead of fp32.
// Block 128x64, BK=16, 8 warps (4x2), warp tile 32x32.
// ---------------------------------------------------------------------------
#define GBM 128
#define GBN 64
#define AST 12

__global__ __launch_bounds__(256) void gemm_pre(
    const uint32_t* __restrict__ Ah, const uint32_t* __restrict__ Al,
    const uint32_t* __restrict__ Bh, const uint32_t* __restrict__ Bl,
    float* __restrict__ C, uint16_t* __restrict__ Ch, uint16_t* __restrict__ Cl,
    int M, int N, int K)
{
    __shared__ uint32_t As[2][GBM * AST];
    __shared__ uint32_t Bs[2][GBN * AST];

    const int Kw   = K >> 1;
    const int tid  = threadIdx.x;
    const int wid  = tid >> 5, lane = tid & 31;
    const int g    = lane >> 2, tig = lane & 3;
    const int wm   = wid & 3, wn = wid >> 2;
    const int row0 = blockIdx.y * GBM, col0 = blockIdx.x * GBN;

    const int ar = tid >> 1, aw = (tid & 1) * 4;   // A: uint4 per thread
    const int br = tid >> 2, bw = (tid & 3) * 2;   // B: uint2 per thread

    const uint32_t* Aph = Ah + (size_t)(row0 + ar) * Kw + aw;
    const uint32_t* Apl = Al + (size_t)(row0 + ar) * Kw + aw;
    const uint32_t* Bph = Bh + (size_t)(col0 + br) * Kw + bw;
    const uint32_t* Bpl = Bl + (size_t)(col0 + br) * Kw + bw;

    float acc[2][4][4];
    #pragma unroll
    for (int i = 0; i < 2; i++)
        #pragma unroll
        for (int j = 0; j < 4; j++)
            #pragma unroll
            for (int c = 0; c < 4; c++) acc[i][j][c] = 0.f;

    uint4 rah = *(const uint4*)Aph;
    uint4 ral = *(const uint4*)Apl;
    uint2 rbh = *(const uint2*)Bph;
    uint2 rbl = *(const uint2*)Bpl;

    for (int kw = 0; kw < Kw; kw += 8) {
        *(uint4*)&As[0][ar*AST + aw] = rah;
        *(uint4*)&As[1][ar*AST + aw] = ral;
        *(uint2*)&Bs[0][br*AST + bw] = rbh;
        *(uint2*)&Bs[1][br*AST + bw] = rbl;
        __syncthreads();

        if (kw + 8 < Kw) {
            rah = *(const uint4*)(Aph + kw + 8);
            ral = *(const uint4*)(Apl + kw + 8);
            rbh = *(const uint2*)(Bph + kw + 8);
            rbl = *(const uint2*)(Bpl + kw + 8);
        }

        uint32_t afh[2][4], afl[2][4], bfh[4][2], bfl[4][2];
        #pragma unroll
        for (int mt = 0; mt < 2; mt++) {
            int rb = (wm * 32 + mt * 16) * AST;
            afh[mt][0] = As[0][rb + g * AST + tig];
            afh[mt][1] = As[0][rb + (g + 8) * AST + tig];
            afh[mt][2] = As[0][rb + g * AST + tig + 4];
            afh[mt][3] = As[0][rb + (g + 8) * AST + tig + 4];
            afl[mt][0] = As[1][rb + g * AST + tig];
            afl[mt][1] = As[1][rb + (g + 8) * AST + tig];
            afl[mt][2] = As[1][rb + g * AST + tig + 4];
            afl[mt][3] = As[1][rb + (g + 8) * AST + tig + 4];
        }
        #pragma unroll
        for (int nt = 0; nt < 4; nt++) {
            int cb = (wn * 32 + nt * 8 + g) * AST;
            bfh[nt][0] = Bs[0][cb + tig];
            bfh[nt][1] = Bs[0][cb + tig + 4];
            bfl[nt][0] = Bs[1][cb + tig];
            bfl[nt][1] = Bs[1][cb + tig + 4];
        }

        #pragma unroll
        for (int mt = 0; mt < 2; mt++)
            #pragma unroll
            for (int nt = 0; nt < 4; nt++) {
                MMA_BF16(acc[mt][nt], afh[mt], bfh[nt]);
                MMA_BF16(acc[mt][nt], afh[mt], bfl[nt]);
                MMA_BF16(acc[mt][nt], afl[mt], bfh[nt]);
            }
        __syncthreads();
    }

    if (Ch) {
        #pragma unroll
        for (int mt = 0; mt < 2; mt++)
            #pragma unroll
            for (int nt = 0; nt < 4; nt++) {
                int row = row0 + wm * 32 + mt * 16 + g;
                int col = col0 + wn * 32 + nt * 8 + 2 * tig;
                uint16_t h0,l0,h1,l1;
                split2(acc[mt][nt][0], h0, l0);
                split2(acc[mt][nt][1], h1, l1);
                ((uint32_t*)Ch)[((size_t)row * N + col) >> 1] = (uint32_t)h0 | ((uint32_t)h1 << 16);
                ((uint32_t*)Cl)[((size_t)row * N + col) >> 1] = (uint32_t)l0 | ((uint32_t)l1 << 16);
                split2(acc[mt][nt][2], h0, l0);
                split2(acc[mt][nt][3], h1, l1);
                ((uint32_t*)Ch)[((size_t)(row + 8) * N + col) >> 1] = (uint32_t)h0 | ((uint32_t)h1 << 16);
                ((uint32_t*)Cl)[((size_t)(row + 8) * N + col) >> 1] = (uint32_t)l0 | ((uint32_t)l1 << 16);
            }
    } else {
        #pragma unroll
        for (int mt = 0; mt < 2; mt++)
            #pragma unroll
            for (int nt = 0; nt < 4; nt++) {
                int row = row0 + wm * 32 + mt * 16 + g;
                int col = col0 + wn * 32 + nt * 8 + 2 * tig;
                *(float2*)(C + (size_t)row * N + col) =
                    make_float2(acc[mt][nt][0], acc[mt][nt][1]);
                *(float2*)(C + (size_t)(row + 8) * N + col) =
                    make_float2(acc[mt][nt][2], acc[mt][nt][3]);
            }
    }
}

// ---------------------------------------------------------------------------
// Fused RMSNorm + RoPE (table lookup) + scale + bf16 split.
// ---------------------------------------------------------------------------
__global__ void rms_rope_split(const float* __restrict__ x,
                               uint16_t* __restrict__ xh,
                               uint16_t* __restrict__ xl,
                               const float* __restrict__ ctab,
                               const float* __restrict__ stab,
                               int nheads, int totalRows, float scale)
{
    int w    = (blockIdx.x * blockDim.x + threadIdx.x) >> 5;
    int lane = threadIdx.x & 31;
    if (w >= totalRows) return;
    int t = (w / nheads) % T_;

    const float* row = x + (size_t)w * HD_;
    float x1 = row[lane], x2 = row[lane + 32];
    float ss = x1 * x1 + x2 * x2;
    #pragma unroll
    for (int o = 16; o; o >>= 1) ss += __shfl_xor_sync(0xffffffffu, ss, o);
    float sc = rsqrtf(ss * (1.0f / HD_) + 1.1920928955078125e-07f);
    x1 *= sc; x2 *= sc;

    float c = ctab[t * 32 + lane], s = stab[t * 32 + lane];
    float o1 = ( x1 * c + x2 * s) * scale;
    float o2 = (-x1 * s + x2 * c) * scale;

    uint16_t h, l;
    split2(o1, h, l);
    xh[(size_t)w * HD_ + lane] = h;      xl[(size_t)w * HD_ + lane] = l;
    split2(o2, h, l);
    xh[(size_t)w * HD_ + lane + 32] = h; xl[(size_t)w * HD_ + lane + 32] = l;
}

// ---------------------------------------------------------------------------
// Tensor-core causal GQA flash attention, split-bf16, no max-subtraction.
// Writes split bf16 y for the out-projection GEMM.
// ---------------------------------------------------------------------------
__global__ __launch_bounds__(128) void flash_tc(
    const uint16_t* __restrict__ qh, const uint16_t* __restrict__ ql,
    const uint16_t* __restrict__ kh, const uint16_t* __restrict__ kl,
    const uint16_t* __restrict__ vh, const uint16_t* __restrict__ vl,
    uint16_t* __restrict__ yh, uint16_t* __restrict__ yl)
{
    __shared__ uint32_t Kh_s[64*36], Kl_s[64*36], Vh_s[64*36], Vl_s[64*36];

    const int b = blockIdx.z, h = blockIdx.y;
    const int m0 = blockIdx.x * 64;
    const int kvh = h >> 1;
    const int tid = threadIdx.x, wid = tid >> 5, lane = tid & 31;
    const int g = lane >> 2, tig = lane & 3;
    const int row0 = m0 + wid * 16;

    const uint32_t* qh32 = (const uint32_t*)qh;
    const uint32_t* ql32 = (const uint32_t*)ql;
    const uint32_t* kh32 = (const uint32_t*)kh;
    const uint32_t* kl32 = (const uint32_t*)kl;
    const uint32_t* vh32 = (const uint32_t*)vh;
    const uint32_t* vl32 = (const uint32_t*)vl;

    uint32_t qfh[4][4], qfl[4][4];
    {
        size_t q0 = ((size_t)(b * T_ + row0 + g) * NH_ + h) * 32;
        size_t q1 = ((size_t)(b * T_ + row0 + g + 8) * NH_ + h) * 32;
        #pragma unroll
        for (int kk = 0; kk < 4; kk++) {
            qfh[kk][0] = qh32[q0 + kk*8 + tig];
            qfh[kk][1] = qh32[q1 + kk*8 + tig];
            qfh[kk][2] = qh32[q0 + kk*8 + 4 + tig];
            qfh[kk][3] = qh32[q1 + kk*8 + 4 + tig];
            qfl[kk][0] = ql32[q0 + kk*8 + tig];
            qfl[kk][1] = ql32[q1 + kk*8 + tig];
            qfl[kk][2] = ql32[q0 + kk*8 + 4 + tig];
            qfl[kk][3] = ql32[q1 + kk*8 + 4 + tig];
        }
    }

    float o[8][4];
    #pragma unroll
    for (int nt = 0; nt < 8; nt++)
        #pragma unroll
        for (int c = 0; c < 4; c++) o[nt][c] = 0.f;
    float lsum0 = 0.f, lsum1 = 0.f;

    uint32_t vh_base = (uint32_t)__cvta_generic_to_shared(Vh_s);
    uint32_t vl_base = (uint32_t)__cvta_generic_to_shared(Vl_s);

    for (int n0 = 0; n0 <= m0; n0 += 64) {
        #pragma unroll
        for (int it = 0; it < 4; it++) {
            int e = it * 128 + tid;
            int j = e >> 3, dq = (e & 7) * 4;
            size_t src = ((size_t)(b * T_ + n0 + j) * NKV_ + kvh) * 32 + dq;
            int dst = j * 36 + dq;
            *(uint4*)&Kh_s[dst] = *(const uint4*)&kh32[src];
            *(uint4*)&Kl_s[dst] = *(const uint4*)&kl32[src];
            *(uint4*)&Vh_s[dst] = *(const uint4*)&vh32[src];
            *(uint4*)&Vl_s[dst] = *(const uint4*)&vl32[src];
        }
        __syncthreads();

        float sfr[8][4];
        #pragma unroll
        for (int nt = 0; nt < 8; nt++) {
            #pragma unroll
            for (int c = 0; c < 4; c++) sfr[nt][c] = 0.f;
            #pragma unroll
            for (int kk = 0; kk < 4; kk++) {
                uint32_t bh[2], bl[2];
                int bw = (nt*8 + g)*36 + kk*8 + tig;
                bh[0] = Kh_s[bw]; bh[1] = Kh_s[bw + 4];
                bl[0] = Kl_s[bw]; bl[1] = Kl_s[bw + 4];
                MMA_BF16(sfr[nt], qfh[kk], bh);
                MMA_BF16(sfr[nt], qfh[kk], bl);
                MMA_BF16(sfr[nt], qfl[kk], bh);
            }
        }

        uint32_t pfh[4][4], pfl[4][4];
        const bool diag = (n0 == m0);
        #pragma unroll
        for (int nt = 0; nt < 8; nt++) {
            float p0 = __expf(sfr[nt][0]);
            float p1 = __expf(sfr[nt][1]);
            float p2 = __expf(sfr[nt][2]);
            float p3 = __expf(sfr[nt][3]);
            if (diag) {
                int col = n0 + nt*8 + 2*tig;
                int r0 = row0 + g, r1 = row0 + g + 8;
                if (col     > r0) p0 = 0.f;
                if (col + 1 > r0) p1 = 0.f;
                if (col     > r1) p2 = 0.f;
                if (col + 1 > r1) p3 = 0.f;
            }
            lsum0 += p0 + p1;
            lsum1 += p2 + p3;
            uint16_t h0,l0,h1,l1,h2,l2,h3,l3;
            split2(p0,h0,l0); split2(p1,h1,l1); split2(p2,h2,l2); split2(p3,h3,l3);
            int kk = nt >> 1, s = (nt & 1) * 2;
            pfh[kk][s]   = (uint32_t)h0 | ((uint32_t)h1 << 16);
            pfh[kk][s+1] = (uint32_t)h2 | ((uint32_t)h3 << 16);
            pfl[kk][s]   = (uint32_t)l0 | ((uint32_t)l1 << 16);
            pfl[kk][s+1] = (uint32_t)l2 | ((uint32_t)l3 << 16);
        }

        #pragma unroll
        for (int nt = 0; nt < 8; nt++) {
            #pragma unroll
            for (int kk = 0; kk < 4; kk++) {
                uint32_t off = ((16*kk + (lane & 15)) * 36 + nt*4) * 4;
                uint32_t bh[2], bl[2];
                LDMX2T(bh[0], bh[1], vh_base + off);
                LDMX2T(bl[0], bl[1], vl_base + off);
                MMA_BF16(o[nt], pfh[kk], bh);
                MMA_BF16(o[nt], pfh[kk], bl);
                MMA_BF16(o[nt], pfl[kk], bh);
            }
        }
        __syncthreads();
    }

    lsum0 += __shfl_xor_sync(0xffffffffu, lsum0, 1);
    lsum0 += __shfl_xor_sync(0xffffffffu, lsum0, 2);
    lsum1 += __shfl_xor_sync(0xffffffffu, lsum1, 1);
    lsum1 += __shfl_xor_sync(0xffffffffu, lsum1, 2);
    float i0 = 1.f / lsum0, i1 = 1.f / lsum1;

    size_t y0 = ((size_t)(b * T_ + row0 + g) * NH_ + h) * HD_;
    size_t y1 = ((size_t)(b * T_ + row0 + g + 8) * NH_ + h) * HD_;
    #pragma unroll
    for (int nt = 0; nt < 8; nt++) {
        int col = nt*8 + 2*tig;
        uint16_t h0,l0,h1,l1;
        split2(o[nt][0] * i0, h0, l0);
        split2(o[nt][1] * i0, h1, l1);
        ((uint32_t*)yh)[(y0 + col) >> 1] = (uint32_t)h0 | ((uint32_t)h1 << 16);
        ((uint32_t*)yl)[(y0 + col) >> 1] = (uint32_t)l0 | ((uint32_t)l1 << 16);
        split2(o[nt][2] * i1, h0, l0);
        split2(o[nt][3] * i1, h1, l1);
        ((uint32_t*)yh)[(y1 + col) >> 1] = (uint32_t)h0 | ((uint32_t)h1 << 16);
        ((uint32_t*)yl)[(y1 + col) >> 1] = (uint32_t)l0 | ((uint32_t)l1 << 16);
    }
}

// ---------------------------------------------------------------------------
extern "C" void kernel_launch(void* const* d_in, const int* in_sizes, int n_in,
                              void* d_out, int out_size)
{
    const float* x  = (const float*)d_in[0];
    const float* Wq = (const float*)d_in[1];
    const float* Wk = (const float*)d_in[2];
    const float* Wv = (const float*)d_in[3];
    const float* Wp = (const float*)d_in[4];
    float* out = (float*)d_out;

    float *q, *k, *ctab, *stab;
    cudaGetSymbolAddress((void**)&q, g_q);
    cudaGetSymbolAddress((void**)&k, g_k);
    cudaGetSymbolAddress((void**)&ctab, g_cos);
    cudaGetSymbolAddress((void**)&stab, g_sin);
    uint16_t *xh,*xl,*qh,*ql,*kh,*kl,*vh,*vl,*yh,*yl;
    uint16_t *wqh,*wql,*wkh,*wkl,*wvh,*wvl,*wph,*wpl;
    cudaGetSymbolAddress((void**)&xh, g_xh);  cudaGetSymbolAddress((void**)&xl, g_xl);
    cudaGetSymbolAddress((void**)&qh, g_qh);  cudaGetSymbolAddress((void**)&ql, g_ql);
    cudaGetSymbolAddress((void**)&kh, g_kh);  cudaGetSymbolAddress((void**)&kl, g_kl);
    cudaGetSymbolAddress((void**)&vh, g_vh);  cudaGetSymbolAddress((void**)&vl, g_vl);
    cudaGetSymbolAddress((void**)&yh, g_yh);  cudaGetSymbolAddress((void**)&yl, g_yl);
    cudaGetSymbolAddress((void**)&wqh, g_wqh); cudaGetSymbolAddress((void**)&wql, g_wql);
    cudaGetSymbolAddress((void**)&wkh, g_wkh); cudaGetSymbolAddress((void**)&wkl, g_wkl);
    cudaGetSymbolAddress((void**)&wvh, g_wvh); cudaGetSymbolAddress((void**)&wvl, g_wvl);
    cudaGetSymbolAddress((void**)&wph, g_wph); cudaGetSymbolAddress((void**)&wpl, g_wpl);

    // pre-split inputs and weights; rope tables
    split4<<<(BT_*DIM_/4 + 255)/256, 256>>>(x,  xh,  xl,  BT_*DIM_/4);
    split4<<<(DIM_*DIM_/4 + 255)/256, 256>>>(Wq, wqh, wql, DIM_*DIM_/4);
    split4<<<(KVD_*DIM_/4 + 255)/256, 256>>>(Wk, wkh, wkl, KVD_*DIM_/4);
    split4<<<(KVD_*DIM_/4 + 255)/256, 256>>>(Wv, wvh, wvl, KVD_*DIM_/4);
    split4<<<(DIM_*DIM_/4 + 255)/256, 256>>>(Wp, wph, wpl, DIM_*DIM_/4);
    rope_tables<<<(T_*32 + 255)/256, 256>>>(ctab, stab);

    // QKV projections (v writes split bf16 directly)
    gemm_pre<<<dim3(DIM_/GBN, BT_/GBM), 256>>>((uint32_t*)xh, (uint32_t*)xl,
        (uint32_t*)wqh, (uint32_t*)wql, q, nullptr, nullptr, BT_, DIM_, DIM_);
    gemm_pre<<<dim3(KVD_/GBN, BT_/GBM), 256>>>((uint32_t*)xh, (uint32_t*)xl,
        (uint32_t*)wkh, (uint32_t*)wkl, k, nullptr, nullptr, BT_, KVD_, DIM_);
    gemm_pre<<<dim3(KVD_/GBN, BT_/GBM), 256>>>((uint32_t*)xh, (uint32_t*)xl,
        (uint32_t*)wvh, (uint32_t*)wvl, nullptr, vh, vl, BT_, KVD_, DIM_);

    // RMSNorm + RoPE + split (q gets 1/8 attention scale folded in)
    rms_rope_split<<<(BT_*NH_*32)/256,  256>>>(q, qh, ql, ctab, stab, NH_,  BT_*NH_,  0.125f);
    rms_rope_split<<<(BT_*NKV_*32)/256, 256>>>(k, kh, kl, ctab, stab, NKV_, BT_*NKV_, 1.0f);

    // Tensor-core causal flash attention (emits split y)
    flash_tc<<<dim3(T_/64, NH_, B_), 128>>>(qh, ql, kh, kl, vh, vl, yh, yl);

    // Output projection
    gemm_pre<<<dim3(DIM_/GBN, BT_/GBM), 256>>>((uint32_t*)yh, (uint32_t*)yl,
        (uint32_t*)wph, (uint32_t*)wpl, out, nullptr, nullptr, BT_, DIM_, DIM_);
}

// round 7
// speedup vs baseline: 1.8043x; 1.8043x over previous
#include <cuda_runtime.h>
#include <cuda_bf16.h>
#include <cuda_fp16.h>
#include <stdint.h>
#include <math.h>

#define B_   8
#define T_   2048
#define DIM_ 512
#define NH_  8
#define NKV_ 4
#define HD_  64
#define KVD_ (NKV_*HD_)
#define BT_  (B_*T_)

// fp32 scratch
__device__ float g_q[(size_t)BT_*DIM_];
__device__ float g_k[(size_t)BT_*KVD_];
__device__ float g_y[(size_t)BT_*DIM_];
// fp16 scratch
__device__ uint16_t g_qf[(size_t)BT_*DIM_];
__device__ uint16_t g_kf[(size_t)BT_*KVD_];
__device__ uint16_t g_vf[(size_t)BT_*KVD_];
// rope tables
__device__ float g_cos[T_*32], g_sin[T_*32];

#define MMA_BF16(d, a, b) asm volatile( \
  "mma.sync.aligned.m16n8k16.row.col.f32.bf16.bf16.f32 " \
  "{%0,%1,%2,%3}, {%4,%5,%6,%7}, {%8,%9}, {%0,%1,%2,%3};\n" \
  : "+f"(d[0]), "+f"(d[1]), "+f"(d[2]), "+f"(d[3]) \
  : "r"(a[0]), "r"(a[1]), "r"(a[2]), "r"(a[3]), "r"(b[0]), "r"(b[1]))

#define MMA_F16(d, a, b) asm volatile( \
  "mma.sync.aligned.m16n8k16.row.col.f32.f16.f16.f32 " \
  "{%0,%1,%2,%3}, {%4,%5,%6,%7}, {%8,%9}, {%0,%1,%2,%3};\n" \
  : "+f"(d[0]), "+f"(d[1]), "+f"(d[2]), "+f"(d[3]) \
  : "r"(a[0]), "r"(a[1]), "r"(a[2]), "r"(a[3]), "r"(b[0]), "r"(b[1]))

#define LDMX2T(r0, r1, a) asm volatile( \
  "ldmatrix.sync.aligned.m8n8.x2.trans.shared.b16 {%0,%1}, [%2];" \
  : "=r"(r0), "=r"(r1) : "r"(a))

__device__ __forceinline__ void split2(float f, uint16_t& h, uint16_t& l)
{
    __nv_bfloat16 hb = __float2bfloat16_rn(f);
    float r = f - __bfloat162float(hb);
    __nv_bfloat16 lb = __float2bfloat16_rn(r);
    h = *(uint16_t*)&hb;
    l = *(uint16_t*)&lb;
}

__device__ __forceinline__ void pack4(float4 f, uint32_t* hi, uint32_t* lo)
{
    uint16_t h0,l0,h1,l1,h2,l2,h3,l3;
    split2(f.x,h0,l0); split2(f.y,h1,l1); split2(f.z,h2,l2); split2(f.w,h3,l3);
    hi[0] = (uint32_t)h0 | ((uint32_t)h1 << 16);
    hi[1] = (uint32_t)h2 | ((uint32_t)h3 << 16);
    lo[0] = (uint32_t)l0 | ((uint32_t)l1 << 16);
    lo[1] = (uint32_t)l2 | ((uint32_t)l3 << 16);
}

__device__ __forceinline__ uint32_t f2h2(float a, float b)
{
    __half2 h = __floats2half2_rn(a, b);
    return *(uint32_t*)&h;
}

// rope cos/sin tables (double-precision freq)
__global__ void rope_tables(float* __restrict__ ctab, float* __restrict__ stab)
{
    int i = blockIdx.x * blockDim.x + threadIdx.x;
    if (i >= T_*32) return;
    int t = i >> 5, j = i & 31;
    double invf = pow(10000.0, -(double)(2*j) / (double)HD_);
    float ang = (float)((double)t * invf);
    float s, c;
    sincosf(ang, &s, &c);
    ctab[i] = c; stab[i] = s;
}

// ---------------------------------------------------------------------------
// bf16 3-split tensor-core GEMM: C[M,N] = A[M,K] @ W[N,K]^T
// If Cf16 != null, epilogue writes fp16 instead of fp32 C.
// ---------------------------------------------------------------------------
#define GBM 128
#define GBN 64
#define AST 12

__global__ __launch_bounds__(256) void gemm_bf16x2(const float* __restrict__ A,
                                                   const float* __restrict__ W,
                                                   float* __restrict__ C,
                                                   uint16_t* __restrict__ Cf16,
                                                   int M, int N, int K)
{
    __shared__ uint32_t As[2][GBM * AST];
    __shared__ uint32_t Bs[2][GBN * AST];

    const int tid  = threadIdx.x;
    const int wid  = tid >> 5, lane = tid & 31;
    const int g    = lane >> 2, tig = lane & 3;
    const int wm   = wid & 3, wn = wid >> 2;
    const int row0 = blockIdx.y * GBM, col0 = blockIdx.x * GBN;

    const int ar0 = (tid) >> 2,       ak0 = (tid & 3);
    const int ar1 = (256 + tid) >> 2, ak1 = (tid & 3);
    const int br  = tid >> 2,         bk  = tid & 3;

    float acc[2][4][4];
    #pragma unroll
    for (int i = 0; i < 2; i++)
        #pragma unroll
        for (int j = 0; j < 4; j++)
            #pragma unroll
            for (int c = 0; c < 4; c++) acc[i][j][c] = 0.f;

    float4 pa0 = *(const float4*)(A + (size_t)(row0 + ar0) * K + ak0 * 4);
    float4 pa1 = *(const float4*)(A + (size_t)(row0 + ar1) * K + ak1 * 4);
    float4 pb  = *(const float4*)(W + (size_t)(col0 + br ) * K + bk  * 4);

    for (int k0 = 0; k0 < K; k0 += 16) {
        uint32_t h[2], l[2];
        pack4(pa0, h, l);
        As[0][ar0 * AST + ak0 * 2] = h[0]; As[0][ar0 * AST + ak0 * 2 + 1] = h[1];
        As[1][ar0 * AST + ak0 * 2] = l[0]; As[1][ar0 * AST + ak0 * 2 + 1] = l[1];
        pack4(pa1, h, l);
        As[0][ar1 * AST + ak1 * 2] = h[0]; As[0][ar1 * AST + ak1 * 2 + 1] = h[1];
        As[1][ar1 * AST + ak1 * 2] = l[0]; As[1][ar1 * AST + ak1 * 2 + 1] = l[1];
        pack4(pb, h, l);
        Bs[0][br * AST + bk * 2] = h[0]; Bs[0][br * AST + bk * 2 + 1] = h[1];
        Bs[1][br * AST + bk * 2] = l[0]; Bs[1][br * AST + bk * 2 + 1] = l[1];
        __syncthreads();

        if (k0 + 16 < K) {
            pa0 = *(const float4*)(A + (size_t)(row0 + ar0) * K + k0 + 16 + ak0 * 4);
            pa1 = *(const float4*)(A + (size_t)(row0 + ar1) * K + k0 + 16 + ak1 * 4);
            pb  = *(const float4*)(W + (size_t)(col0 + br ) * K + k0 + 16 + bk  * 4);
        }

        uint32_t afh[2][4], afl[2][4], bfh[4][2], bfl[4][2];
        #pragma unroll
        for (int mt = 0; mt < 2; mt++) {
            int rb = (wm * 32 + mt * 16) * AST;
            afh[mt][0] = As[0][rb + g * AST + tig];
            afh[mt][1] = As[0][rb + (g + 8) * AST + tig];
            afh[mt][2] = As[0][rb + g * AST + tig + 4];
            afh[mt][3] = As[0][rb + (g + 8) * AST + tig + 4];
            afl[mt][0] = As[1][rb + g * AST + tig];
            afl[mt][1] = As[1][rb + (g + 8) * AST + tig];
            afl[mt][2] = As[1][rb + g * AST + tig + 4];
            afl[mt][3] = As[1][rb + (g + 8) * AST + tig + 4];
        }
        #pragma unroll
        for (int nt = 0; nt < 4; nt++) {
            int cb = (wn * 32 + nt * 8 + g) * AST;
            bfh[nt][0] = Bs[0][cb + tig];
            bfh[nt][1] = Bs[0][cb + tig + 4];
            bfl[nt][0] = Bs[1][cb + tig];
            bfl[nt][1] = Bs[1][cb + tig + 4];
        }

        #pragma unroll
        for (int mt = 0; mt < 2; mt++)
            #pragma unroll
            for (int nt = 0; nt < 4; nt++) {
                MMA_BF16(acc[mt][nt], afh[mt], bfh[nt]);
                MMA_BF16(acc[mt][nt], afh[mt], bfl[nt]);
                MMA_BF16(acc[mt][nt], afl[mt], bfh[nt]);
            }
        __syncthreads();
    }

    if (Cf16) {
        #pragma unroll
        for (int mt = 0; mt < 2; mt++)
            #pragma unroll
            for (int nt = 0; nt < 4; nt++) {
                int row = row0 + wm * 32 + mt * 16 + g;
                int col = col0 + wn * 32 + nt * 8 + 2 * tig;
                ((uint32_t*)Cf16)[((size_t)row * N + col) >> 1] =
                    f2h2(acc[mt][nt][0], acc[mt][nt][1]);
                ((uint32_t*)Cf16)[((size_t)(row + 8) * N + col) >> 1] =
                    f2h2(acc[mt][nt][2], acc[mt][nt][3]);
            }
    } else {
        #pragma unroll
        for (int mt = 0; mt < 2; mt++)
            #pragma unroll
            for (int nt = 0; nt < 4; nt++) {
                int row = row0 + wm * 32 + mt * 16 + g;
                int col = col0 + wn * 32 + nt * 8 + 2 * tig;
                *(float2*)(C + (size_t)row * N + col) =
                    make_float2(acc[mt][nt][0], acc[mt][nt][1]);
                *(float2*)(C + (size_t)(row + 8) * N + col) =
                    make_float2(acc[mt][nt][2], acc[mt][nt][3]);
            }
    }
}

// ---------------------------------------------------------------------------
// Fused RMSNorm + RoPE (table) + scale -> fp16. One launch covers q and k.
// ---------------------------------------------------------------------------
__global__ void rms_rope_f16(const float* __restrict__ qsrc,
                             const float* __restrict__ ksrc,
                             uint16_t* __restrict__ qdst,
                             uint16_t* __restrict__ kdst,
                             const float* __restrict__ ctab,
                             const float* __restrict__ stab)
{
    int w    = (blockIdx.x * blockDim.x + threadIdx.x) >> 5;
    int lane = threadIdx.x & 31;
    const int QROWS = BT_ * NH_;
    if (w >= QROWS + BT_ * NKV_) return;

    const float* src;
    uint16_t* dst;
    int t;
    float scale;
    if (w < QROWS) {
        src = qsrc + (size_t)w * HD_;
        dst = qdst + (size_t)w * HD_;
        t = (w / NH_) % T_;
        scale = 0.125f;
    } else {
        int wk = w - QROWS;
        src = ksrc + (size_t)wk * HD_;
        dst = kdst + (size_t)wk * HD_;
        t = (wk / NKV_) % T_;
        scale = 1.0f;
    }

    float x1 = src[lane], x2 = src[lane + 32];
    float ss = x1 * x1 + x2 * x2;
    #pragma unroll
    for (int o = 16; o; o >>= 1) ss += __shfl_xor_sync(0xffffffffu, ss, o);
    float sc = rsqrtf(ss * (1.0f / HD_) + 1.1920928955078125e-07f);
    x1 *= sc; x2 *= sc;

    float c = ctab[t * 32 + lane], s = stab[t * 32 + lane];
    float o1 = ( x1 * c + x2 * s) * scale;
    float o2 = (-x1 * s + x2 * c) * scale;

    __half h1 = __float2half_rn(o1), h2 = __float2half_rn(o2);
    dst[lane]      = *(uint16_t*)&h1;
    dst[lane + 32] = *(uint16_t*)&h2;
}

// ---------------------------------------------------------------------------
// Tensor-core causal GQA flash attention, single-product fp16.
// |s| <= 8 -> p in [e^-8, e^8]: inside fp16 normal range, no max needed.
// BM=64 rows/block, 4 warps x 16 rows. BN=64 KV tile. smem stride 36 words.
// ---------------------------------------------------------------------------
__global__ __launch_bounds__(128) void flash_tc(
    const uint16_t* __restrict__ qf, const uint16_t* __restrict__ kf,
    const uint16_t* __restrict__ vf, float* __restrict__ y)
{
    __shared__ uint32_t K_s[64*36], V_s[64*36];

    const int b = blockIdx.z, h = blockIdx.y;
    const int m0 = blockIdx.x * 64;
    const int kvh = h >> 1;
    const int tid = threadIdx.x, wid = tid >> 5, lane = tid & 31;
    const int g = lane >> 2, tig = lane & 3;
    const int row0 = m0 + wid * 16;

    const uint32_t* q32 = (const uint32_t*)qf;
    const uint32_t* k32 = (const uint32_t*)kf;
    const uint32_t* v32 = (const uint32_t*)vf;

    // persistent Q a-fragments
    uint32_t qfr[4][4];
    {
        size_t q0 = ((size_t)(b * T_ + row0 + g) * NH_ + h) * 32;
        size_t q1 = ((size_t)(b * T_ + row0 + g + 8) * NH_ + h) * 32;
        #pragma unroll
        for (int kk = 0; kk < 4; kk++) {
            qfr[kk][0] = q32[q0 + kk*8 + tig];
            qfr[kk][1] = q32[q1 + kk*8 + tig];
            qfr[kk][2] = q32[q0 + kk*8 + 4 + tig];
            qfr[kk][3] = q32[q1 + kk*8 + 4 + tig];
        }
    }

    float o[8][4];
    #pragma unroll
    for (int nt = 0; nt < 8; nt++)
        #pragma unroll
        for (int c = 0; c < 4; c++) o[nt][c] = 0.f;
    float lsum0 = 0.f, lsum1 = 0.f;

    uint32_t v_base = (uint32_t)__cvta_generic_to_shared(V_s);

    for (int n0 = 0; n0 <= m0; n0 += 64) {
        // cooperative tile load: 64 rows x 8 uint4 each for K and V (512 uint4)
        #pragma unroll
        for (int it = 0; it < 4; it++) {
            int e = it * 128 + tid;
            int j = e >> 3, dq = (e & 7) * 4;
            size_t src = ((size_t)(b * T_ + n0 + j) * NKV_ + kvh) * 32 + dq;
            int dst = j * 36 + dq;
            *(uint4*)&K_s[dst] = *(const uint4*)&k32[src];
            *(uint4*)&V_s[dst] = *(const uint4*)&v32[src];
        }
        __syncthreads();

        // S = Q K^T  (single fp16 product)
        float sfr[8][4];
        #pragma unroll
        for (int nt = 0; nt < 8; nt++) {
            #pragma unroll
            for (int c = 0; c < 4; c++) sfr[nt][c] = 0.f;
            #pragma unroll
            for (int kk = 0; kk < 4; kk++) {
                uint32_t bb[2];
                int bw = (nt*8 + g)*36 + kk*8 + tig;
                bb[0] = K_s[bw]; bb[1] = K_s[bw + 4];
                MMA_F16(sfr[nt], qfr[kk], bb);
            }
        }

        // mask + exp + rowsum, pack P into fp16 a-frags (registers only)
        uint32_t pfr[4][4];
        const bool diag = (n0 == m0);
        #pragma unroll
        for (int nt = 0; nt < 8; nt++) {
            float p0 = __expf(sfr[nt][0]);
            float p1 = __expf(sfr[nt][1]);
            float p2 = __expf(sfr[nt][2]);
            float p3 = __expf(sfr[nt][3]);
            if (diag) {
                int col = n0 + nt*8 + 2*tig;
                int r0 = row0 + g, r1 = row0 + g + 8;
                if (col     > r0) p0 = 0.f;
                if (col + 1 > r0) p1 = 0.f;
                if (col     > r1) p2 = 0.f;
                if (col + 1 > r1) p3 = 0.f;
            }
            lsum0 += p0 + p1;
            lsum1 += p2 + p3;
            int kk = nt >> 1, s = (nt & 1) * 2;
            pfr[kk][s]   = f2h2(p0, p1);
            pfr[kk][s+1] = f2h2(p2, p3);
        }

        // O += P V  (V b-frags via ldmatrix.trans, single fp16 product)
        #pragma unroll
        for (int nt = 0; nt < 8; nt++) {
            #pragma unroll
            for (int kk = 0; kk < 4; kk++) {
                uint32_t off = ((16*kk + (lane & 15)) * 36 + nt*4) * 4;
                uint32_t bb[2];
                LDMX2T(bb[0], bb[1], v_base + off);
                MMA_F16(o[nt], pfr[kk], bb);
            }
        }
        __syncthreads();
    }

    lsum0 += __shfl_xor_sync(0xffffffffu, lsum0, 1);
    lsum0 += __shfl_xor_sync(0xffffffffu, lsum0, 2);
    lsum1 += __shfl_xor_sync(0xffffffffu, lsum1, 1);
    lsum1 += __shfl_xor_sync(0xffffffffu, lsum1, 2);
    float i0 = 1.f / lsum0, i1 = 1.f / lsum1;

    float* y0 = y + ((size_t)(b * T_ + row0 + g) * NH_ + h) * HD_;
    float* y1 = y + ((size_t)(b * T_ + row0 + g + 8) * NH_ + h) * HD_;
    #pragma unroll
    for (int nt = 0; nt < 8; nt++) {
        int col = nt*8 + 2*tig;
        *(float2*)(y0 + col) = make_float2(o[nt][0] * i0, o[nt][1] * i0);
        *(float2*)(y1 + col) = make_float2(o[nt][2] * i1, o[nt][3] * i1);
    }
}

// ---------------------------------------------------------------------------
extern "C" void kernel_launch(void* const* d_in, const int* in_sizes, int n_in,
                              void* d_out, int out_size)
{
    const float* x  = (const float*)d_in[0];
    const float* Wq = (const float*)d_in[1];
    const float* Wk = (const float*)d_in[2];
    const float* Wv = (const float*)d_in[3];
    const float* Wp = (const float*)d_in[4];
    float* out = (float*)d_out;

    float *q, *k, *y, *ctab, *stab;
    cudaGetSymbolAddress((void**)&q, g_q);
    cudaGetSymbolAddress((void**)&k, g_k);
    cudaGetSymbolAddress((void**)&y, g_y);
    cudaGetSymbolAddress((void**)&ctab, g_cos);
    cudaGetSymbolAddress((void**)&stab, g_sin);
    uint16_t *qf, *kf, *vf;
    cudaGetSymbolAddress((void**)&qf, g_qf);
    cudaGetSymbolAddress((void**)&kf, g_kf);
    cudaGetSymbolAddress((void**)&vf, g_vf);

    // QKV projections (bf16 3-split; V writes fp16 directly)
    gemm_bf16x2<<<dim3(DIM_/GBN, BT_/GBM), 256>>>(x, Wq, q, nullptr, BT_, DIM_, DIM_);
    gemm_bf16x2<<<dim3(KVD_/GBN, BT_/GBM), 256>>>(x, Wk, k, nullptr, BT_, KVD_, DIM_);
    gemm_bf16x2<<<dim3(KVD_/GBN, BT_/GBM), 256>>>(x, Wv, nullptr, vf, BT_, KVD_, DIM_);

    // rope tables, then fused rmsnorm+rope -> fp16 q,k (one launch)
    rope_tables<<<(T_*32 + 255)/256, 256>>>(ctab, stab);
    rms_rope_f16<<<((BT_*NH_ + BT_*NKV_)*32 + 255)/256, 256>>>(q, k, qf, kf, ctab, stab);

    // fp16 tensor-core causal flash attention
    flash_tc<<<dim3(T_/64, NH_, B_), 128>>>(qf, kf, vf, y);

    // Output projection
    gemm_bf16x2<<<dim3(DIM_/GBN, BT_/GBM), 256>>>(y, Wp, out, nullptr, BT_, DIM_, DIM_);
}